// round 4
// baseline (speedup 1.0000x reference)
#include <cuda_runtime.h>
#include <cuda_fp16.h>
#include <math.h>

#define N_USER   100000
#define N_ITEM   50000
#define NTOT     150000
#define EMB      64
#define EMB2     32          // half2 / float2 elements per row
#define FEAT     384
#define NNZ      2400000
#define N_PROMPT 8
#define EPS_V    1e-8f

#define SCAN_B   1024
#define NBLK     ((NTOT + SCAN_B - 1) / SCAN_B)   // 147

#define GEMM_BLOCKS 296
#define EGO_BLOCKS  ((N_USER * 32 + 255) / 256)   // 12500
#define HIST_BLOCKS ((NNZ + 255) / 256)           // 9375
#define FRONT_BLOCKS (GEMM_BLOCKS + EGO_BLOCKS + HIST_BLOCKS)

// ---------------- scratch (device globals; no allocation allowed) -------------
// g_count / g_cursor are zero at module load and re-zeroed by k_final each run.
__device__ int     g_count[NTOT];
__device__ int     g_cursor[NTOT];
__device__ int     g_rowptr[NTOT + 1];
__device__ int     g_bsum[256];
__device__ int2    g_perm[NNZ];                  // (col, val-as-int) packed 8B
__device__ float2  g_ego[(size_t)NTOT * EMB2];   // fp32 ego (final acc)
__device__ __half2 g_ego_h[(size_t)NTOT * EMB2]; // fp16 ego (gather + dot)
__device__ __half2 g_xh[4][(size_t)NTOT * EMB2]; // per-layer propagated x (fp16)
__device__ float   g_egonorm[NTOT];

// ---------------- fused front: item GEMM + user ego + edge histogram ----------
// One launch; roles by blockIdx (GEMM first so long-running blocks start early).
__global__ __launch_bounds__(256)
void k_front(const float* __restrict__ A, const float* __restrict__ W,
             const float* __restrict__ bias,
             const float2* __restrict__ uf, const float* __restrict__ pe,
             const int* __restrict__ rows) {
    extern __shared__ float smem[];
    int bid = blockIdx.x;

    if (bid < GEMM_BLOCKS) {
        // ---- item GEMM: tanh(A[50000,384] @ W[384,64] + b), W in shared ----
        float* s_w = smem;                 // FEAT*EMB
        float* s_b = smem + FEAT * EMB;    // EMB
        for (int idx = threadIdx.x; idx < FEAT * EMB; idx += blockDim.x)
            s_w[idx] = W[idx];
        if (threadIdx.x < EMB) s_b[threadIdx.x] = bias[threadIdx.x];
        __syncthreads();

        int lane = threadIdx.x & 31;
        int warp = threadIdx.x >> 5;
        for (int row = bid * 8 + warp; row < N_ITEM; row += GEMM_BLOCKS * 8) {
            const float* Ar = A + (size_t)row * FEAT;
            float acc0 = 0.f, acc1 = 0.f;
#pragma unroll 4
            for (int kk = 0; kk < FEAT; kk += 4) {
                float4 a = *(const float4*)(Ar + kk);           // broadcast
                const float* wp = s_w + kk * EMB + 2 * lane;    // cols {2l,2l+1}
                float2 w0 = *(const float2*)(wp);
                float2 w1 = *(const float2*)(wp + EMB);
                float2 w2 = *(const float2*)(wp + 2 * EMB);
                float2 w3 = *(const float2*)(wp + 3 * EMB);
                acc0 += a.x * w0.x; acc1 += a.x * w0.y;
                acc0 += a.y * w1.x; acc1 += a.y * w1.y;
                acc0 += a.z * w2.x; acc1 += a.z * w2.y;
                acc0 += a.w * w3.x; acc1 += a.w * w3.y;
            }
            float v0 = tanhf(acc0 + s_b[2 * lane]);
            float v1 = tanhf(acc1 + s_b[2 * lane + 1]);
            size_t o = (size_t)(N_USER + row) * EMB2 + lane;
            g_ego[o]   = make_float2(v0, v1);
            g_ego_h[o] = __floats2half2_rn(v0, v1);
            float sq = v0 * v0 + v1 * v1;
#pragma unroll
            for (int s = 16; s; s >>= 1) sq += __shfl_xor_sync(~0u, sq, s);
            if (lane == 0) g_egonorm[N_USER + row] = sqrtf(sq);
        }
    } else if (bid < GEMM_BLOCKS + EGO_BLOCKS) {
        // ---- user ego: uf + prompt_sum, fp32 + fp16 copies, fused norm ----
        int lb = bid - GEMM_BLOCKS;
        float* sp = smem;                  // EMB floats
        if (threadIdx.x < EMB) {
            float s = 0.f;
#pragma unroll
            for (int p = 0; p < N_PROMPT; ++p) s += pe[p * EMB + threadIdx.x];
            sp[threadIdx.x] = s;
        }
        __syncthreads();
        int row  = (lb * 256 + threadIdx.x) >> 5;
        int lane = threadIdx.x & 31;
        if (row >= N_USER) return;
        size_t o = (size_t)row * EMB2 + lane;
        float2 v = uf[o];
        v.x += sp[2 * lane];
        v.y += sp[2 * lane + 1];
        g_ego[o]   = v;
        g_ego_h[o] = __floats2half2_rn(v.x, v.y);
        float sq = v.x * v.x + v.y * v.y;
#pragma unroll
        for (int s = 16; s; s >>= 1) sq += __shfl_xor_sync(~0u, sq, s);
        if (lane == 0) g_egonorm[row] = sqrtf(sq);
    } else {
        // ---- edge histogram ----
        int e = (bid - GEMM_BLOCKS - EGO_BLOCKS) * 256 + threadIdx.x;
        if (e < NNZ) atomicAdd(&g_count[rows[e]], 1);
    }
}

// ---------------- scan ---------------------------------------------------------
__global__ void k_scan_block() {
    __shared__ int s[SCAN_B];
    int t = threadIdx.x;
    int i = blockIdx.x * SCAN_B + t;
    int v = (i < NTOT) ? g_count[i] : 0;
    s[t] = v;
    __syncthreads();
    for (int off = 1; off < SCAN_B; off <<= 1) {
        int u = (t >= off) ? s[t - off] : 0;
        __syncthreads();
        s[t] += u;
        __syncthreads();
    }
    if (i < NTOT) g_rowptr[i] = s[t] - v;        // exclusive within block
    if (t == SCAN_B - 1) g_bsum[blockIdx.x] = s[t];
}

// each block redundantly scans the 147 block sums, adds its own offset
__global__ void k_scan_fix() {
    __shared__ int s[256];
    int t = threadIdx.x;
    int v = (t < NBLK) ? g_bsum[t] : 0;
    s[t] = v;
    __syncthreads();
    for (int off = 1; off < 256; off <<= 1) {
        int u = (t >= off) ? s[t - off] : 0;
        __syncthreads();
        s[t] += u;
        __syncthreads();
    }
    int boff = (blockIdx.x == 0) ? 0 : s[blockIdx.x - 1];
    for (int i = t; i < SCAN_B; i += 256) {
        int idx = blockIdx.x * SCAN_B + i;
        if (idx < NTOT) g_rowptr[idx] += boff;
    }
    if (blockIdx.x == 0 && t == 0) g_rowptr[NTOT] = NNZ;
}

__global__ void k_scatter(const int* __restrict__ rows,
                          const int* __restrict__ cols,
                          const float* __restrict__ vals) {
    int e = blockIdx.x * blockDim.x + threadIdx.x;
    if (e >= NNZ) return;
    int r = rows[e];
    int pos = g_rowptr[r] + atomicAdd(&g_cursor[r], 1);
    g_perm[pos] = make_int2(cols[e], __float_as_int(vals[e]));
}

// ---------------- fused SpMM + cosine reweight (fp16 gather) ------------------
// Warp per row; edge metadata via int4 (2 edges / LDG.128); deep gather unroll.
__global__ __launch_bounds__(256)
void k_spmm(const __half2* __restrict__ xin, __half2* __restrict__ xout) {
    int row  = (blockIdx.x * blockDim.x + threadIdx.x) >> 5;
    int lane = threadIdx.x & 31;
    if (row >= NTOT) return;
    int beg = g_rowptr[row], end = g_rowptr[row + 1];
    float a0 = 0.f, a1 = 0.f;
    int e = beg;
    if ((e & 1) && e < end) {                  // align to 16B for int4 loads
        int2 ed = g_perm[e];
        float2 f = __half22float2(__ldg(&xin[(size_t)ed.x * EMB2 + lane]));
        float v = __int_as_float(ed.y);
        a0 += v * f.x; a1 += v * f.y;
        ++e;
    }
    for (; e + 4 <= end; e += 4) {             // 4 gathers in flight
        int4 pa = *(const int4*)&g_perm[e];      // edges e, e+1
        int4 pb = *(const int4*)&g_perm[e + 2];  // edges e+2, e+3
        float2 f0 = __half22float2(__ldg(&xin[(size_t)pa.x * EMB2 + lane]));
        float2 f1 = __half22float2(__ldg(&xin[(size_t)pa.z * EMB2 + lane]));
        float2 f2 = __half22float2(__ldg(&xin[(size_t)pb.x * EMB2 + lane]));
        float2 f3 = __half22float2(__ldg(&xin[(size_t)pb.z * EMB2 + lane]));
        float v0 = __int_as_float(pa.y), v1 = __int_as_float(pa.w);
        float v2 = __int_as_float(pb.y), v3 = __int_as_float(pb.w);
        a0 += v0 * f0.x; a1 += v0 * f0.y;
        a0 += v1 * f1.x; a1 += v1 * f1.y;
        a0 += v2 * f2.x; a1 += v2 * f2.y;
        a0 += v3 * f3.x; a1 += v3 * f3.y;
    }
    if (e + 2 <= end) {
        int4 pa = *(const int4*)&g_perm[e];
        float2 f0 = __half22float2(__ldg(&xin[(size_t)pa.x * EMB2 + lane]));
        float2 f1 = __half22float2(__ldg(&xin[(size_t)pa.z * EMB2 + lane]));
        float v0 = __int_as_float(pa.y), v1 = __int_as_float(pa.w);
        a0 += v0 * f0.x; a1 += v0 * f0.y;
        a0 += v1 * f1.x; a1 += v1 * f1.y;
        e += 2;
    }
    if (e < end) {
        int2 ed = g_perm[e];
        float2 f = __half22float2(__ldg(&xin[(size_t)ed.x * EMB2 + lane]));
        float v = __int_as_float(ed.y);
        a0 += v * f.x; a1 += v * f.y;
    }
    size_t o = (size_t)row * EMB2 + lane;
    float2 ef = __half22float2(g_ego_h[o]);
    float dot = a0 * ef.x + a1 * ef.y;
    float sq  = a0 * a0 + a1 * a1;
#pragma unroll
    for (int s = 16; s; s >>= 1) {
        dot += __shfl_xor_sync(~0u, dot, s);
        sq  += __shfl_xor_sync(~0u, sq, s);
    }
    float w = dot / fmaxf(sqrtf(sq) * g_egonorm[row], EPS_V);
    xout[o] = __floats2half2_rn(a0 * w, a1 * w);
}

// ------- final accumulate: out = ego + x1..x4; also re-zero hist scratch ------
__global__ __launch_bounds__(256)
void k_final(float2* __restrict__ out) {
    size_t i = (size_t)blockIdx.x * blockDim.x + threadIdx.x;
    if (i < NTOT) { g_count[i] = 0; g_cursor[i] = 0; }   // ready for next run
    if (i >= (size_t)NTOT * EMB2) return;
    float2 a = g_ego[i];
#pragma unroll
    for (int l = 0; l < 4; ++l) {
        float2 x = __half22float2(g_xh[l][i]);
        a.x += x.x; a.y += x.y;
    }
    out[i] = a;
}

// ---------------- launch ------------------------------------------------------
extern "C" void kernel_launch(void* const* d_in, const int* in_sizes, int n_in,
                              void* d_out, int out_size) {
    const float* user_fea = (const float*)d_in[0];
    const float* item_fea = (const float*)d_in[1];
    const float* prompt   = (const float*)d_in[2];
    const float* mlp_w    = (const float*)d_in[3];
    const float* mlp_b    = (const float*)d_in[4];
    const int*   rows     = (const int*)d_in[5];
    const int*   cols     = (const int*)d_in[6];
    const float* vals     = (const float*)d_in[7];
    float2* out = (float2*)d_out;

    void *p_egoh, *p_xh;
    cudaGetSymbolAddress(&p_egoh, g_ego_h);
    cudaGetSymbolAddress(&p_xh, g_xh);
    __half2* xh = (__half2*)p_xh;
    const size_t XSTRIDE = (size_t)NTOT * EMB2;

    const int front_smem = (FEAT * EMB + EMB) * (int)sizeof(float);  // 98560 B
    cudaFuncSetAttribute(k_front, cudaFuncAttributeMaxDynamicSharedMemorySize,
                         front_smem);

    // 1: fused GEMM + user-ego + histogram (independent work overlapped)
    k_front<<<FRONT_BLOCKS, 256, front_smem>>>(
        item_fea, mlp_w, mlp_b, (const float2*)user_fea, prompt, rows);
    // 2-3: row-pointer scan
    k_scan_block<<<NBLK, SCAN_B>>>();
    k_scan_fix<<<NBLK, 256>>>();
    // 4: CSR scatter
    k_scatter<<<(NNZ + 255) / 256, 256>>>(rows, cols, vals);

    // 5-8: propagation layers (fp16 gather, fused cosine reweight)
    const int spmm_blocks = (NTOT * 32 + 255) / 256;   // warp per row
    k_spmm<<<spmm_blocks, 256>>>((const __half2*)p_egoh, xh);
    k_spmm<<<spmm_blocks, 256>>>(xh,               xh + XSTRIDE);
    k_spmm<<<spmm_blocks, 256>>>(xh + XSTRIDE,     xh + 2 * XSTRIDE);
    k_spmm<<<spmm_blocks, 256>>>(xh + 2 * XSTRIDE, xh + 3 * XSTRIDE);

    // 9: out = ego + sum of layers (+ re-zero scratch for next run)
    k_final<<<(int)((XSTRIDE + 255) / 256), 256>>>(out);
}